// round 15
// baseline (speedup 1.0000x reference)
#include <cuda_runtime.h>
#include <cstdint>

// RWKV7 chunked attention, B=4 T=2048 H=32 C=64 dT=16.
// One CTA (512 thr) per (b,h). Producer/consumer pipeline; ALL GEMMs on
// mma.sync tf32 with fragment-permuted smem layouts (float4 operand loads).
// R14: transposed tiles use stride 20 (16B-aligned rows) — fixes R13 fault.

#define B_ 4
#define T_ 2048
#define H_ 32
#define C_ 64
#define DT_ 16
#define NT_ 128
#define THREADS 512

typedef unsigned long long u64;

#define TS20 20             // transposed-tile row stride (floats), 16B aligned

// ---- shared layout (float words) ----
#define OFF_S    0          // [64][68], cols permuted pc64
#define OFF_UT   4352       // [64][20] tf32 u^T, cols permuted pc16
#define OFF_ABU  5632       // [16][68] logical
#define OFF_YP   6720       // [16][68] logical
#define OFF_LPP  7808       // [4][64]
#define OFF_BUF  8064
// per-buffer offsets:
#define BWAQ 0              // [32][68] tf32, cols pc64 (wa rows 0-15, wq 16-31)
#define BKWQ 2176           // [32][68] tf32, cols pc64 (bwi rows 0-15, kwi 16-31)
#define BVT  4352           // [64][20] tf32 v^T, cols pc16
#define BKWT 5632           // [64][20] tf32 kwi^T, pc16
#define BBWT 6912           // [64][20] tf32 bwi^T, pc16
#define BAKV 8192           // [16][68] logical
#define BQKV 9280           // [16][68] logical
#define BD32 10368          // [32][36]: ab logical / qb pc16 / ak,qk 16+pc16
#define BFW  11520          // [64] logical
#define BUF_STRIDE 11584
#define OFF_ACCV (OFF_BUF + 2 * BUF_STRIDE)   // 2 x [64][68] logical
#define SMEM_WORDS (OFF_ACCV + 2 * 4352)
#define SMEM_BYTES (SMEM_WORDS * 4)

#define BARC() asm volatile("bar.sync 1, 256;" ::: "memory")
#define BARP() asm volatile("bar.sync 2, 256;" ::: "memory")

__device__ __forceinline__ int pc64(int c) {
    return (c & 3) * 16 + ((c >> 2) & 1) * 8 + (c >> 3);
}
__device__ __forceinline__ int pc16(int t) {
    return (t & 3) * 4 + (t >> 2);
}

__device__ __forceinline__ float4 ld4(const float* p) { return *reinterpret_cast<const float4*>(p); }
__device__ __forceinline__ void st4(float* p, float4 v) { *reinterpret_cast<float4*>(p) = v; }

__device__ __forceinline__ float tf32r(float x) {
    uint32_t r; asm("cvt.rna.tf32.f32 %0, %1;" : "=r"(r) : "f"(x));
    return __uint_as_float(r);
}
__device__ __forceinline__ void mma8(float4& d, float a0, float a1, float a2,
                                     float a3, float b0, float b1) {
    asm volatile(
        "mma.sync.aligned.m16n8k8.row.col.f32.tf32.tf32.f32 "
        "{%0,%1,%2,%3}, {%4,%5,%6,%7}, {%8,%9}, {%0,%1,%2,%3};"
        : "+f"(d.x), "+f"(d.y), "+f"(d.z), "+f"(d.w)
        : "r"(__float_as_uint(a0)), "r"(__float_as_uint(a1)),
          "r"(__float_as_uint(a2)), "r"(__float_as_uint(a3)),
          "r"(__float_as_uint(b0)), "r"(__float_as_uint(b1)));
}

// ---------- producer ----------
__device__ __forceinline__ void produce(
    float* __restrict__ sm, float* __restrict__ buf, float* __restrict__ av,
    const float* __restrict__ gw, const float* __restrict__ gq,
    const float* __restrict__ gk, const float* __restrict__ gv,
    const float* __restrict__ ga, const float* __restrict__ gb,
    int b, int h, int cp, int pt)
{
    const int th = pt >> 6;
    const int cl = pt & 63;
    const size_t strT = (size_t)H_ * C_;
    const int wmp  = pt >> 5;
    const int lane = pt & 31;
    const int gid  = lane >> 2;
    const int tq   = lane & 3;
    const int pcl  = pc64(cl);

    // ---- stage ----
    {
        size_t base = (((size_t)b * T_ + cp * DT_ + 4 * th) * H_ + h) * C_ + cl;
        float rw[4], rq[4], rk[4], rv[4], ra[4], rb[4];
        #pragma unroll
        for (int r = 0; r < 4; r++) {
            size_t ix = base + (size_t)r * strT;
            rw[r] = gw[ix]; rq[r] = gq[ix]; rk[r] = gk[ix];
            rv[r] = gv[ix]; ra[r] = ga[ix]; rb[r] = gb[ix];
        }
        float wd[4]; float lp = 1.f;
        #pragma unroll
        for (int r = 0; r < 4; r++) { wd[r] = __expf(-__expf(rw[r])); lp *= wd[r]; }
        sm[OFF_LPP + th * 64 + cl] = lp;
        BARP();
        float incl = 1.f;
        #pragma unroll
        for (int gg = 0; gg < 3; gg++)
            if (gg < th) incl *= sm[OFF_LPP + gg * 64 + cl];
        #pragma unroll
        for (int r = 0; r < 4; r++) {
            int t = 4 * th + r;
            float ip = incl; incl *= wd[r];
            float rinv = __fdividef(1.f, incl);
            float kw = tf32r(rk[r] * rinv);
            float bw = tf32r(rb[r] * rinv);
            int pct = pc16(t);
            buf[BWAQ + t * 68 + pcl]        = tf32r(ra[r] * ip);
            buf[BWAQ + (16 + t) * 68 + pcl] = tf32r(rq[r] * incl);
            buf[BKWQ + t * 68 + pcl]        = bw;
            buf[BKWQ + (16 + t) * 68 + pcl] = kw;
            buf[BVT  + cl * TS20 + pct] = tf32r(rv[r]);
            buf[BKWT + cl * TS20 + pct] = kw;
            buf[BBWT + cl * TS20 + pct] = bw;
        }
        if (th == 3) buf[BFW + cl] = incl;
    }
    BARP();

    // ---- grams via mma: D32 = [wa;wq] @ [bwi;kwi]^T ----
    {
        const int mt = wmp & 1;
        const int nb = wmp >> 1;
        float A0[16], A1[16], B0[16];
        {
            const float* p0 = buf + BWAQ + (16 * mt + gid) * 68 + tq * 16;
            const float* p1 = p0 + 8 * 68;
            const float* pb = buf + BKWQ + (8 * nb + gid) * 68 + tq * 16;
            #pragma unroll
            for (int g = 0; g < 4; g++) {
                *reinterpret_cast<float4*>(&A0[4 * g]) = ld4(p0 + 4 * g);
                *reinterpret_cast<float4*>(&A1[4 * g]) = ld4(p1 + 4 * g);
                *reinterpret_cast<float4*>(&B0[4 * g]) = ld4(pb + 4 * g);
            }
        }
        float4 Cv = {0.f, 0.f, 0.f, 0.f};
        #pragma unroll
        for (int k = 0; k < 8; k++)
            mma8(Cv, A0[k], A1[k], A0[8 + k], A1[8 + k], B0[k], B0[8 + k]);
        const int t0 = gid, t1 = gid + 8;
        const int C0 = 8 * nb + 2 * tq, C1 = C0 + 1;
        const int s0 = C0 & 15, s1 = C1 & 15;
        float m00, m01, m10, m11;
        if (mt == 0) { m00 = (t0 > s0); m01 = (t0 > s1); m10 = (t1 > s0); m11 = (t1 > s1); }
        else         { m00 = (t0 >= s0); m01 = (t0 >= s1); m10 = (t1 >= s0); m11 = (t1 >= s1); }
        int dc0, dc1;
        if (C0 < 16) { dc0 = (mt == 0) ? C0 : pc16(C0); dc1 = (mt == 0) ? C1 : pc16(C1); }
        else         { dc0 = 16 + pc16(C0 - 16);        dc1 = 16 + pc16(C1 - 16); }
        float* D = buf + BD32;
        D[(16 * mt + gid)     * 36 + dc0] = tf32r(Cv.x * m00);
        D[(16 * mt + gid)     * 36 + dc1] = tf32r(Cv.y * m01);
        D[(16 * mt + gid + 8) * 36 + dc0] = tf32r(Cv.z * m10);
        D[(16 * mt + gid + 8) * 36 + dc1] = tf32r(Cv.w * m11);
    }
    BARP();

    // ---- AKV/QKV via mma: [ak;qk](32x16) @ v(16x64) ----
    {
        const int mt = wmp & 1;
        const int n0 = 16 * (wmp >> 1);
        float4 P0 = ld4(buf + BD32 + (16 * mt + gid) * 36 + 16 + tq * 4);
        float4 P1 = ld4(buf + BD32 + (16 * mt + gid + 8) * 36 + 16 + tq * 4);
        float4 Q0 = ld4(buf + BVT + (n0 + gid) * TS20 + tq * 4);
        float4 Q1 = ld4(buf + BVT + (n0 + 8 + gid) * TS20 + tq * 4);
        float4 C0v = {0.f, 0.f, 0.f, 0.f};
        float4 C1v = {0.f, 0.f, 0.f, 0.f};
        mma8(C0v, P0.x, P1.x, P0.y, P1.y, Q0.x, Q0.y);
        mma8(C0v, P0.z, P1.z, P0.w, P1.w, Q0.z, Q0.w);
        mma8(C1v, P0.x, P1.x, P0.y, P1.y, Q1.x, Q1.y);
        mma8(C1v, P0.z, P1.z, P0.w, P1.w, Q1.z, Q1.w);
        float* dst = buf + (mt == 0 ? BAKV : BQKV);
        *reinterpret_cast<float2*>(dst + gid * 68 + n0 + 2 * tq)           = make_float2(C0v.x, C0v.y);
        *reinterpret_cast<float2*>(dst + (gid + 8) * 68 + n0 + 2 * tq)     = make_float2(C0v.z, C0v.w);
        *reinterpret_cast<float2*>(dst + gid * 68 + n0 + 8 + 2 * tq)       = make_float2(C1v.x, C1v.y);
        *reinterpret_cast<float2*>(dst + (gid + 8) * 68 + n0 + 8 + 2 * tq) = make_float2(C1v.z, C1v.w);
    }

    // ---- ACCV via mma: v^T(64x16) @ kwi(16x64) -> av logical ----
    {
        const int m0 = 16 * (wmp >> 1);
        const int nbase = 32 * (wmp & 1);
        float4 P0 = ld4(buf + BVT + (m0 + gid) * TS20 + tq * 4);
        float4 P1 = ld4(buf + BVT + (m0 + gid + 8) * TS20 + tq * 4);
        #pragma unroll
        for (int j = 0; j < 4; j++) {
            const int n = nbase + 8 * j;
            float4 Q = ld4(buf + BKWT + (n + gid) * TS20 + tq * 4);
            float4 Cv = {0.f, 0.f, 0.f, 0.f};
            mma8(Cv, P0.x, P1.x, P0.y, P1.y, Q.x, Q.y);
            mma8(Cv, P0.z, P1.z, P0.w, P1.w, Q.z, Q.w);
            *reinterpret_cast<float2*>(av + (m0 + gid) * 68 + n + 2 * tq)     = make_float2(Cv.x, Cv.y);
            *reinterpret_cast<float2*>(av + (m0 + gid + 8) * 68 + n + 2 * tq) = make_float2(Cv.z, Cv.w);
        }
    }
}

__global__ __launch_bounds__(THREADS, 1)
void rwkv7_kernel(const float* __restrict__ gw, const float* __restrict__ gq,
                  const float* __restrict__ gk, const float* __restrict__ gv,
                  const float* __restrict__ ga, const float* __restrict__ gb,
                  const float* __restrict__ gs0, float* __restrict__ gy)
{
    extern __shared__ __align__(16) float sm[];

    const int bh  = blockIdx.x;
    const int b   = bh / H_;
    const int h   = bh % H_;
    const int tid = threadIdx.x;
    const bool is_prod = tid >= 256;
    const int pt = tid & 255;

    const int w    = pt >> 5;
    const int lane = pt & 31;
    const int mt   = w & 1;
    const int nb   = w >> 1;
    const int gid  = lane >> 2;
    const int tq   = lane & 3;

    // ---- bootstrap ----
    if (is_prod) {
        produce(sm, sm + OFF_BUF, sm + OFF_ACCV, gw, gq, gk, gv, ga, gb, b, h, 0, pt);
    } else {
        const float* s0p = gs0 + (size_t)bh * 4096;
        #pragma unroll
        for (int q4 = pt; q4 < 1024; q4 += 256) {
            int row = q4 >> 4, j0 = (q4 & 15) * 4;
            float4 v = ld4(s0p + row * 64 + j0);
            sm[OFF_S + row * 68 + pc64(j0)]     = v.x;
            sm[OFF_S + row * 68 + pc64(j0 + 1)] = v.y;
            sm[OFF_S + row * 68 + pc64(j0 + 2)] = v.z;
            sm[OFF_S + row * 68 + pc64(j0 + 3)] = v.w;
        }
    }
    __syncthreads();

    for (int ch = 0; ch < NT_; ch++) {
        const int p = ch & 1;

        if (is_prod) {
            if (ch + 1 < NT_)
                produce(sm, sm + OFF_BUF + (p ^ 1) * BUF_STRIDE,
                        sm + OFF_ACCV + (p ^ 1) * 4352,
                        gw, gq, gk, gv, ga, gb, b, h, ch + 1, pt);
        } else {
            float* buf = sm + OFF_BUF + p * BUF_STRIDE;
            float* av  = sm + OFF_ACCV + p * 4352;

            // ===== state GEMM via mma: D = [wa;wq] @ S^T =====
            {
                float A0[16], A1[16];
                {
                    const float* p0 = buf + BWAQ + (16 * mt + gid) * 68 + tq * 16;
                    const float* p1 = p0 + 8 * 68;
                    #pragma unroll
                    for (int g = 0; g < 4; g++) {
                        *reinterpret_cast<float4*>(&A0[4 * g]) = ld4(p0 + 4 * g);
                        *reinterpret_cast<float4*>(&A1[4 * g]) = ld4(p1 + 4 * g);
                    }
                }
                float* dst = (mt == 0) ? (sm + OFF_ABU) : (sm + OFF_YP);
                #pragma unroll
                for (int tile = 0; tile < 2; tile++) {
                    const int n0 = 16 * nb + 8 * tile;
                    float Bv[16];
                    const float* pb = sm + OFF_S + (n0 + gid) * 68 + tq * 16;
                    #pragma unroll
                    for (int g = 0; g < 4; g++)
                        *reinterpret_cast<float4*>(&Bv[4 * g]) = ld4(pb + 4 * g);
                    float4 Cv = {0.f, 0.f, 0.f, 0.f};
                    #pragma unroll
                    for (int k = 0; k < 8; k++)
                        mma8(Cv, A0[k], A1[k], A0[8 + k], A1[8 + k], Bv[k], Bv[8 + k]);
                    *reinterpret_cast<float2*>(dst + gid * 68 + n0 + 2 * tq)       = make_float2(Cv.x, Cv.y);
                    *reinterpret_cast<float2*>(dst + (gid + 8) * 68 + n0 + 2 * tq) = make_float2(Cv.z, Cv.w);
                }
            }
            BARC();   // abu/yp ready

            // ===== solve (I-ab) u = abu+AKV (64 columns, 2 warps) =====
            if (pt < 64) {
                const int c = pt;
                float uu[DT_];
                #pragma unroll
                for (int t = 0; t < DT_; t++)
                    uu[t] = sm[OFF_ABU + t * 68 + c] + buf[BAKV + t * 68 + c];
                #pragma unroll
                for (int t = 1; t < DT_; t++) {
                    float a0 = uu[t], a1 = 0.f, a2 = 0.f, a3 = 0.f;
                    const float* abr = buf + BD32 + t * 36;
                    #pragma unroll
                    for (int s4 = 0; 4 * s4 < t; s4++) {
                        float4 abq = ld4(abr + 4 * s4);
                        int s = 4 * s4;
                        if (s     < t) a0 += abq.x * uu[s];
                        if (s + 1 < t) a1 += abq.y * uu[s + 1];
                        if (s + 2 < t) a2 += abq.z * uu[s + 2];
                        if (s + 3 < t) a3 += abq.w * uu[s + 3];
                    }
                    uu[t] = (a0 + a1) + (a2 + a3);
                }
                #pragma unroll
                for (int t = 0; t < DT_; t++)
                    sm[OFF_UT + c * TS20 + pc16(t)] = tf32r(uu[t]);
            }
            BARC();   // u ready

            // ===== y via mma: y = qb@u + YP + QKV =====
            {
                const int n0 = 8 * w;
                float4 P0 = ld4(buf + BD32 + (16 + gid) * 36 + tq * 4);
                float4 P1 = ld4(buf + BD32 + (16 + gid + 8) * 36 + tq * 4);
                float4 Q  = ld4(sm + OFF_UT + (n0 + gid) * TS20 + tq * 4);
                float4 Cv = {0.f, 0.f, 0.f, 0.f};
                mma8(Cv, P0.x, P1.x, P0.y, P1.y, Q.x, Q.y);
                mma8(Cv, P0.z, P1.z, P0.w, P1.w, Q.z, Q.w);
                const int c0 = n0 + 2 * tq;
                float2 yp0 = *reinterpret_cast<const float2*>(sm + OFF_YP + gid * 68 + c0);
                float2 yp1 = *reinterpret_cast<const float2*>(sm + OFF_YP + (gid + 8) * 68 + c0);
                float2 qk0 = *reinterpret_cast<const float2*>(buf + BQKV + gid * 68 + c0);
                float2 qk1 = *reinterpret_cast<const float2*>(buf + BQKV + (gid + 8) * 68 + c0);
                size_t y0 = (((size_t)b * T_ + ch * DT_ + gid) * H_ + h) * C_ + c0;
                size_t y1 = (((size_t)b * T_ + ch * DT_ + gid + 8) * H_ + h) * C_ + c0;
                __stcs(reinterpret_cast<float2*>(gy + y0),
                       make_float2(Cv.x + yp0.x + qk0.x, Cv.y + yp0.y + qk0.y));
                __stcs(reinterpret_cast<float2*>(gy + y1),
                       make_float2(Cv.z + yp1.x + qk1.x, Cv.w + yp1.y + qk1.y));
            }

            // ===== ACCU via mma + fused state update =====
            {
                const int m0 = 16 * (w >> 1);
                const int nbase = 32 * (w & 1);
                float4 P0 = ld4(sm + OFF_UT + (m0 + gid) * TS20 + tq * 4);
                float4 P1 = ld4(sm + OFF_UT + (m0 + gid + 8) * TS20 + tq * 4);
                #pragma unroll
                for (int j = 0; j < 4; j++) {
                    const int n = nbase + 8 * j;
                    float4 Q = ld4(buf + BBWT + (n + gid) * TS20 + tq * 4);
                    float4 Cv = {0.f, 0.f, 0.f, 0.f};
                    mma8(Cv, P0.x, P1.x, P0.y, P1.y, Q.x, Q.y);
                    mma8(Cv, P0.z, P1.z, P0.w, P1.w, Q.z, Q.w);
                    const int c0 = n + 2 * tq;
                    float2 fw2 = *reinterpret_cast<const float2*>(buf + BFW + c0);
                    float2 av0 = *reinterpret_cast<const float2*>(av + (m0 + gid) * 68 + c0);
                    float2 av1 = *reinterpret_cast<const float2*>(av + (m0 + gid + 8) * 68 + c0);
                    const int pj0 = pc64(c0), pj1 = pc64(c0 + 1);
                    float* s0p = sm + OFF_S + (m0 + gid) * 68;
                    float* s1p = sm + OFF_S + (m0 + gid + 8) * 68;
                    s0p[pj0] = (s0p[pj0] + av0.x + Cv.x) * fw2.x;
                    s0p[pj1] = (s0p[pj1] + av0.y + Cv.y) * fw2.y;
                    s1p[pj0] = (s1p[pj0] + av1.x + Cv.z) * fw2.x;
                    s1p[pj1] = (s1p[pj1] + av1.y + Cv.w) * fw2.y;
                }
            }
        }
        __syncthreads();   // buffer handoff + S visibility
    }
}

extern "C" void kernel_launch(void* const* d_in, const int* in_sizes, int n_in,
                              void* d_out, int out_size)
{
    const float* w  = (const float*)d_in[0];
    const float* q  = (const float*)d_in[1];
    const float* k  = (const float*)d_in[2];
    const float* v  = (const float*)d_in[3];
    const float* a  = (const float*)d_in[4];
    const float* b  = (const float*)d_in[5];
    const float* s0 = (const float*)d_in[6];
    float* y = (float*)d_out;

    cudaFuncSetAttribute(rwkv7_kernel, cudaFuncAttributeMaxDynamicSharedMemorySize, SMEM_BYTES);
    rwkv7_kernel<<<B_ * H_, THREADS, SMEM_BYTES>>>(w, q, k, v, a, b, s0, y);
}

// round 16
// speedup vs baseline: 1.0158x; 1.0158x over previous
#include <cuda_runtime.h>
#include <cstdint>

// RWKV7 chunked attention, B=4 T=2048 H=32 C=64 dT=16.
// One CTA (512 thr) per (b,h). Producer/consumer pipeline; GEMMs on mma.sync
// tf32. R15: pc64 fragment-permutation applied ONLY to stride-68 tiles
// (S, BWAQ, BKWQ) -> ld4 operand loads for state GEMM + grams; transposed
// tiles stay at conflict-free stride 17 with scalar access (as champion R12).

#define B_ 4
#define T_ 2048
#define H_ 32
#define C_ 64
#define DT_ 16
#define NT_ 128
#define THREADS 512

typedef unsigned long long u64;

// ---- shared layout (float words) ----
#define OFF_S    0          // [64][68], cols pc64-permuted
#define OFF_U    4352       // [16][64] tg swizzle (exact u, for y)
#define OFF_UT   5376       // [64][17] tf32 u^T (plain t cols)
#define OFF_ABU  6464       // [16][68] logical
#define OFF_YP   7552       // [16][68] logical
#define OFF_LPP  8640       // [4][64]
#define OFF_BUF  8896
// per-buffer offsets:
#define BWAQ 0              // [32][68] tf32, cols pc64 (wa rows 0-15, wq 16-31)
#define BKWQ 2176           // [32][68] tf32, cols pc64 (bwi rows 0-15, kwi 16-31)
#define BVT  4352           // [64][17] tf32 v^T (plain t cols)
#define BKWT 5440           // [64][17] tf32 kwi^T
#define BBWT 6528           // [64][17] tf32 bwi^T
#define BAKV 7616           // [16][68] logical
#define BQKV 8704           // [16][68] logical
#define BD32 9792           // [32][36] logical masked grams: ab|ak / qb|qk
#define BFW  10944          // [64] logical
#define BUF_STRIDE 11008
#define OFF_ACCV (OFF_BUF + 2 * BUF_STRIDE)   // 2 x [64][68] logical
#define SMEM_WORDS (OFF_ACCV + 2 * 4352)
#define SMEM_BYTES (SMEM_WORDS * 4)

#define BARC() asm volatile("bar.sync 1, 256;" ::: "memory")   // consumer group
#define BARP() asm volatile("bar.sync 2, 256;" ::: "memory")   // producer group

// xor swizzle for [16][64] tile (u in tg layout for y phase)
__device__ __forceinline__ int tg(int t, int f)  { return t * 64 + (((f ^ t) & 15) << 2); }
__device__ __forceinline__ int tw(int t, int c)  { return t * 64 + ((((c >> 2) ^ t) & 15) << 2) + (c & 3); }
// fragment permutation: col c -> (c&3)*16 + ((c>>2)&1)*8 + (c>>3)
__device__ __forceinline__ int pc64(int c) {
    return (c & 3) * 16 + ((c >> 2) & 1) * 8 + (c >> 3);
}

__device__ __forceinline__ float4 ld4(const float* p) { return *reinterpret_cast<const float4*>(p); }
__device__ __forceinline__ void st4(float* p, float4 v) { *reinterpret_cast<float4*>(p) = v; }
__device__ __forceinline__ ulonglong2 ldp(const float* p) { return *reinterpret_cast<const ulonglong2*>(p); }

__device__ __forceinline__ u64 pk2(float lo, float hi) {
    u64 r; asm("mov.b64 %0, {%1, %2};" : "=l"(r) : "f"(lo), "f"(hi)); return r;
}
__device__ __forceinline__ void un2(u64 v, float& lo, float& hi) {
    asm("mov.b64 {%0, %1}, %2;" : "=f"(lo), "=f"(hi) : "l"(v));
}
__device__ __forceinline__ void fma2(u64& d, u64 a, u64 b) {
    asm("fma.rn.f32x2 %0, %1, %2, %0;" : "+l"(d) : "l"(a), "l"(b));
}
__device__ __forceinline__ float tf32r(float x) {
    uint32_t r; asm("cvt.rna.tf32.f32 %0, %1;" : "=r"(r) : "f"(x));
    return __uint_as_float(r);
}
__device__ __forceinline__ void mma8f(float4& d, float a0, float a1, float a2,
                                      float a3, float b0, float b1) {
    asm volatile(
        "mma.sync.aligned.m16n8k8.row.col.f32.tf32.tf32.f32 "
        "{%0,%1,%2,%3}, {%4,%5,%6,%7}, {%8,%9}, {%0,%1,%2,%3};"
        : "+f"(d.x), "+f"(d.y), "+f"(d.z), "+f"(d.w)
        : "r"(__float_as_uint(a0)), "r"(__float_as_uint(a1)),
          "r"(__float_as_uint(a2)), "r"(__float_as_uint(a3)),
          "r"(__float_as_uint(b0)), "r"(__float_as_uint(b1)));
}
__device__ __forceinline__ uint32_t fu(float x) { return __float_as_uint(x); }

// ---------- producer ----------
__device__ __forceinline__ void produce(
    float* __restrict__ sm, float* __restrict__ buf, float* __restrict__ av,
    const float* __restrict__ gw, const float* __restrict__ gq,
    const float* __restrict__ gk, const float* __restrict__ gv,
    const float* __restrict__ ga, const float* __restrict__ gb,
    int b, int h, int cp, int pt)
{
    const int th = pt >> 6;
    const int cl = pt & 63;
    const size_t strT = (size_t)H_ * C_;
    const int wmp  = pt >> 5;
    const int lane = pt & 31;
    const int gid  = lane >> 2;
    const int tq   = lane & 3;
    const int pcl  = pc64(cl);

    // ---- stage ----
    {
        size_t base = (((size_t)b * T_ + cp * DT_ + 4 * th) * H_ + h) * C_ + cl;
        float rw[4], rq[4], rk[4], rv[4], ra[4], rb[4];
        #pragma unroll
        for (int r = 0; r < 4; r++) {
            size_t ix = base + (size_t)r * strT;
            rw[r] = gw[ix]; rq[r] = gq[ix]; rk[r] = gk[ix];
            rv[r] = gv[ix]; ra[r] = ga[ix]; rb[r] = gb[ix];
        }
        float wd[4]; float lp = 1.f;
        #pragma unroll
        for (int r = 0; r < 4; r++) { wd[r] = __expf(-__expf(rw[r])); lp *= wd[r]; }
        sm[OFF_LPP + th * 64 + cl] = lp;
        BARP();
        float incl = 1.f;
        #pragma unroll
        for (int gg = 0; gg < 3; gg++)
            if (gg < th) incl *= sm[OFF_LPP + gg * 64 + cl];
        #pragma unroll
        for (int r = 0; r < 4; r++) {
            int t = 4 * th + r;
            float ip = incl; incl *= wd[r];
            float rinv = __fdividef(1.f, incl);
            float kw = tf32r(rk[r] * rinv);
            float bw = tf32r(rb[r] * rinv);
            buf[BWAQ + t * 68 + pcl]        = tf32r(ra[r] * ip);
            buf[BWAQ + (16 + t) * 68 + pcl] = tf32r(rq[r] * incl);
            buf[BKWQ + t * 68 + pcl]        = bw;
            buf[BKWQ + (16 + t) * 68 + pcl] = kw;
            buf[BVT  + cl * 17 + t] = tf32r(rv[r]);
            buf[BKWT + cl * 17 + t] = kw;
            buf[BBWT + cl * 17 + t] = bw;
        }
        if (th == 3) buf[BFW + cl] = incl;
    }
    BARP();

    // ---- grams via mma: D32 = [wa;wq] @ [bwi;kwi]^T (ld4 fragment loads) ----
    {
        const int mt = wmp & 1;
        const int nb = wmp >> 1;
        float A0[16], A1[16], B0[16];
        {
            const float* p0 = buf + BWAQ + (16 * mt + gid) * 68 + tq * 16;
            const float* p1 = p0 + 8 * 68;
            const float* pb = buf + BKWQ + (8 * nb + gid) * 68 + tq * 16;
            #pragma unroll
            for (int g = 0; g < 4; g++) {
                *reinterpret_cast<float4*>(&A0[4 * g]) = ld4(p0 + 4 * g);
                *reinterpret_cast<float4*>(&A1[4 * g]) = ld4(p1 + 4 * g);
                *reinterpret_cast<float4*>(&B0[4 * g]) = ld4(pb + 4 * g);
            }
        }
        float4 Cv = {0.f, 0.f, 0.f, 0.f};
        #pragma unroll
        for (int k = 0; k < 8; k++)
            mma8f(Cv, A0[k], A1[k], A0[8 + k], A1[8 + k], B0[k], B0[8 + k]);
        const int t0 = gid, t1 = gid + 8;
        const int C0 = 8 * nb + 2 * tq, C1 = C0 + 1;
        const int s0 = C0 & 15, s1 = C1 & 15;
        float m00, m01, m10, m11;
        if (mt == 0) { m00 = (t0 > s0); m01 = (t0 > s1); m10 = (t1 > s0); m11 = (t1 > s1); }
        else         { m00 = (t0 >= s0); m01 = (t0 >= s1); m10 = (t1 >= s0); m11 = (t1 >= s1); }
        float* D = buf + BD32;
        D[(16 * mt + gid)     * 36 + C0] = tf32r(Cv.x * m00);
        D[(16 * mt + gid)     * 36 + C1] = tf32r(Cv.y * m01);
        D[(16 * mt + gid + 8) * 36 + C0] = tf32r(Cv.z * m10);
        D[(16 * mt + gid + 8) * 36 + C1] = tf32r(Cv.w * m11);
    }
    BARP();

    // ---- AKV/QKV via mma: [ak;qk](32x16) @ v(16x64) (R12 verbatim) ----
    {
        const int mt = wmp & 1;
        const int n0 = 16 * (wmp >> 1);
        const float* Ar = buf + BD32 + (16 * mt + gid) * 36 + 16;
        float4 C0v = {0.f, 0.f, 0.f, 0.f};
        float4 C1v = {0.f, 0.f, 0.f, 0.f};
        #pragma unroll
        for (int k = 0; k < 2; k++) {
            const int ca = 8 * k + tq;
            float a0 = Ar[ca], a1 = Ar[8 * 36 + ca];
            float a2 = Ar[ca + 4], a3 = Ar[8 * 36 + ca + 4];
            float b00 = buf[BVT + (n0 + gid) * 17 + ca];
            float b01 = buf[BVT + (n0 + gid) * 17 + ca + 4];
            float b10 = buf[BVT + (n0 + 8 + gid) * 17 + ca];
            float b11 = buf[BVT + (n0 + 8 + gid) * 17 + ca + 4];
            mma8f(C0v, a0, a1, a2, a3, b00, b01);
            mma8f(C1v, a0, a1, a2, a3, b10, b11);
        }
        float* dst = buf + (mt == 0 ? BAKV : BQKV);
        *reinterpret_cast<float2*>(dst + gid * 68 + n0 + 2 * tq)           = make_float2(C0v.x, C0v.y);
        *reinterpret_cast<float2*>(dst + (gid + 8) * 68 + n0 + 2 * tq)     = make_float2(C0v.z, C0v.w);
        *reinterpret_cast<float2*>(dst + gid * 68 + n0 + 8 + 2 * tq)       = make_float2(C1v.x, C1v.y);
        *reinterpret_cast<float2*>(dst + (gid + 8) * 68 + n0 + 8 + 2 * tq) = make_float2(C1v.z, C1v.w);
    }

    // ---- ACCV via mma: v^T(64x16) @ kwi(16x64) -> av logical (R12 verbatim) ----
    {
        const int m0 = 16 * (wmp >> 1);
        const int nbase = 32 * (wmp & 1);
        float4 Cv[4] = {{0,0,0,0}, {0,0,0,0}, {0,0,0,0}, {0,0,0,0}};
        #pragma unroll
        for (int k = 0; k < 2; k++) {
            const int ca = 8 * k + tq;
            float a0 = buf[BVT + (m0 + gid) * 17 + ca];
            float a1 = buf[BVT + (m0 + gid + 8) * 17 + ca];
            float a2 = buf[BVT + (m0 + gid) * 17 + ca + 4];
            float a3 = buf[BVT + (m0 + gid + 8) * 17 + ca + 4];
            #pragma unroll
            for (int j = 0; j < 4; j++) {
                const int n = nbase + 8 * j;
                float b0 = buf[BKWT + (n + gid) * 17 + ca];
                float b1 = buf[BKWT + (n + gid) * 17 + ca + 4];
                mma8f(Cv[j], a0, a1, a2, a3, b0, b1);
            }
        }
        #pragma unroll
        for (int j = 0; j < 4; j++) {
            const int n = nbase + 8 * j;
            *reinterpret_cast<float2*>(av + (m0 + gid) * 68 + n + 2 * tq)     = make_float2(Cv[j].x, Cv[j].y);
            *reinterpret_cast<float2*>(av + (m0 + gid + 8) * 68 + n + 2 * tq) = make_float2(Cv[j].z, Cv[j].w);
        }
    }
}

__global__ __launch_bounds__(THREADS, 1)
void rwkv7_kernel(const float* __restrict__ gw, const float* __restrict__ gq,
                  const float* __restrict__ gk, const float* __restrict__ gv,
                  const float* __restrict__ ga, const float* __restrict__ gb,
                  const float* __restrict__ gs0, float* __restrict__ gy)
{
    extern __shared__ __align__(16) float sm[];

    const int bh  = blockIdx.x;
    const int b   = bh / H_;
    const int h   = bh % H_;
    const int tid = threadIdx.x;
    const bool is_prod = tid >= 256;
    const int pt = tid & 255;

    // consumer mappings
    const int w    = pt >> 5;
    const int tx   = (w & 3) * 4 + ((pt >> 3) & 3);   // y phase: t
    const int iq   = ((w >> 2) & 1) * 8 + (pt & 7);   // y phase: i-quad
    const int lane = pt & 31;
    const int mt   = w & 1;
    const int nb   = w >> 1;
    const int gid  = lane >> 2;
    const int tq   = lane & 3;

    // ---- bootstrap ----
    if (is_prod) {
        produce(sm, sm + OFF_BUF, sm + OFF_ACCV, gw, gq, gk, gv, ga, gb, b, h, 0, pt);
    } else {
        const float* s0p = gs0 + (size_t)bh * 4096;
        #pragma unroll
        for (int q4 = pt; q4 < 1024; q4 += 256) {
            int row = q4 >> 4, j0 = (q4 & 15) * 4;
            float4 v = ld4(s0p + row * 64 + j0);
            sm[OFF_S + row * 68 + pc64(j0)]     = v.x;
            sm[OFF_S + row * 68 + pc64(j0 + 1)] = v.y;
            sm[OFF_S + row * 68 + pc64(j0 + 2)] = v.z;
            sm[OFF_S + row * 68 + pc64(j0 + 3)] = v.w;
        }
    }
    __syncthreads();

    for (int ch = 0; ch < NT_; ch++) {
        const int p = ch & 1;

        if (is_prod) {
            if (ch + 1 < NT_)
                produce(sm, sm + OFF_BUF + (p ^ 1) * BUF_STRIDE,
                        sm + OFF_ACCV + (p ^ 1) * 4352,
                        gw, gq, gk, gv, ga, gb, b, h, ch + 1, pt);
        } else {
            float* buf = sm + OFF_BUF + p * BUF_STRIDE;
            float* av  = sm + OFF_ACCV + p * 4352;

            // ===== state GEMM via mma: D = [wa;wq] @ S^T (ld4 fragments) =====
            {
                float A0[16], A1[16];
                {
                    const float* p0 = buf + BWAQ + (16 * mt + gid) * 68 + tq * 16;
                    const float* p1 = p0 + 8 * 68;
                    #pragma unroll
                    for (int g = 0; g < 4; g++) {
                        *reinterpret_cast<float4*>(&A0[4 * g]) = ld4(p0 + 4 * g);
                        *reinterpret_cast<float4*>(&A1[4 * g]) = ld4(p1 + 4 * g);
                    }
                }
                float* dst = (mt == 0) ? (sm + OFF_ABU) : (sm + OFF_YP);
                #pragma unroll
                for (int tile = 0; tile < 2; tile++) {
                    const int n0 = 16 * nb + 8 * tile;
                    float Bv[16];
                    const float* pb = sm + OFF_S + (n0 + gid) * 68 + tq * 16;
                    #pragma unroll
                    for (int g = 0; g < 4; g++)
                        *reinterpret_cast<float4*>(&Bv[4 * g]) = ld4(pb + 4 * g);
                    float4 Cv = {0.f, 0.f, 0.f, 0.f};
                    #pragma unroll
                    for (int k = 0; k < 8; k++)
                        mma8f(Cv, A0[k], A1[k], A0[8 + k], A1[8 + k], Bv[k], Bv[8 + k]);
                    *reinterpret_cast<float2*>(dst + gid * 68 + n0 + 2 * tq)       = make_float2(Cv.x, Cv.y);
                    *reinterpret_cast<float2*>(dst + (gid + 8) * 68 + n0 + 2 * tq) = make_float2(Cv.z, Cv.w);
                }
            }
            BARC();   // abu/yp ready

            // ===== solve (I-ab) u = abu+AKV (64 columns, 2 warps) — R12 verbatim =====
            if (pt < 64) {
                const int c = pt;
                float uu[DT_];
                #pragma unroll
                for (int t = 0; t < DT_; t++)
                    uu[t] = sm[OFF_ABU + t * 68 + c] + buf[BAKV + t * 68 + c];
                #pragma unroll
                for (int t = 1; t < DT_; t++) {
                    float a0 = uu[t], a1 = 0.f, a2 = 0.f, a3 = 0.f;
                    const float* abr = buf + BD32 + t * 36;
                    #pragma unroll
                    for (int s4 = 0; 4 * s4 < t; s4++) {
                        float4 abq = ld4(abr + 4 * s4);
                        int s = 4 * s4;
                        if (s     < t) a0 += abq.x * uu[s];
                        if (s + 1 < t) a1 += abq.y * uu[s + 1];
                        if (s + 2 < t) a2 += abq.z * uu[s + 2];
                        if (s + 3 < t) a3 += abq.w * uu[s + 3];
                    }
                    uu[t] = (a0 + a1) + (a2 + a3);
                }
                #pragma unroll
                for (int t = 0; t < DT_; t++) {
                    sm[OFF_U + tw(t, c)] = uu[t];
                    sm[OFF_UT + c * 17 + t] = tf32r(uu[t]);
                }
            }
            BARC();   // u ready

            // ===== y = yp + QKV + qb@u — R12 verbatim =====
            {
                float4 ypv = ld4(sm + OFF_YP + tx * 68 + 4 * iq);
                float4 qkv = ld4(buf + BQKV + tx * 68 + 4 * iq);
                float4 qbr[4];
                #pragma unroll
                for (int r = 0; r < 4; r++)
                    qbr[r] = ld4(buf + BD32 + (16 + tx) * 36 + 4 * r);
                u64 y01 = pk2(ypv.x + qkv.x, ypv.y + qkv.y);
                u64 y23 = pk2(ypv.z + qkv.z, ypv.w + qkv.w);
                #pragma unroll
                for (int s = 0; s < 16; s++) {
                    float qbs = (s & 2) ? ((s & 1) ? qbr[s >> 2].w : qbr[s >> 2].z)
                                        : ((s & 1) ? qbr[s >> 2].y : qbr[s >> 2].x);
                    ulonglong2 U2 = ldp(sm + OFF_U + tg(s, iq));
                    u64 q2 = pk2(qbs, qbs);
                    fma2(y01, q2, U2.x);
                    fma2(y23, q2, U2.y);
                }
                float o0, o1, o2, o3;
                un2(y01, o0, o1); un2(y23, o2, o3);
                size_t yb = (((size_t)b * T_ + ch * DT_ + tx) * H_ + h) * C_ + 4 * iq;
                __stcs(reinterpret_cast<float4*>(gy + yb), make_float4(o0, o1, o2, o3));
            }

            // ===== ACCU via mma + fused state update (S writeback permuted) =====
            {
                const int m0 = 16 * (w >> 1);
                const int nbase = 32 * (w & 1);
                float4 Cv[4] = {{0,0,0,0}, {0,0,0,0}, {0,0,0,0}, {0,0,0,0}};
                #pragma unroll
                for (int k = 0; k < 2; k++) {
                    const int ca = 8 * k + tq;
                    float a0 = sm[OFF_UT + (m0 + gid) * 17 + ca];
                    float a1 = sm[OFF_UT + (m0 + gid + 8) * 17 + ca];
                    float a2 = sm[OFF_UT + (m0 + gid) * 17 + ca + 4];
                    float a3 = sm[OFF_UT + (m0 + gid + 8) * 17 + ca + 4];
                    #pragma unroll
                    for (int j = 0; j < 4; j++) {
                        const int n = nbase + 8 * j;
                        float b0 = buf[BBWT + (n + gid) * 17 + ca];
                        float b1 = buf[BBWT + (n + gid) * 17 + ca + 4];
                        mma8f(Cv[j], a0, a1, a2, a3, b0, b1);
                    }
                }
                #pragma unroll
                for (int j = 0; j < 4; j++) {
                    const int n = nbase + 8 * j;
                    const int c0 = n + 2 * tq;
                    float2 fw2 = *reinterpret_cast<const float2*>(buf + BFW + c0);
                    float2 av0 = *reinterpret_cast<const float2*>(av + (m0 + gid) * 68 + c0);
                    float2 av1 = *reinterpret_cast<const float2*>(av + (m0 + gid + 8) * 68 + c0);
                    const int pj0 = pc64(c0), pj1 = pc64(c0 + 1);
                    float* s0p = sm + OFF_S + (m0 + gid) * 68;
                    float* s1p = sm + OFF_S + (m0 + gid + 8) * 68;
                    s0p[pj0] = (s0p[pj0] + av0.x + Cv[j].x) * fw2.x;
                    s0p[pj1] = (s0p[pj1] + av0.y + Cv[j].y) * fw2.y;
                    s1p[pj0] = (s1p[pj0] + av1.x + Cv[j].z) * fw2.x;
                    s1p[pj1] = (s1p[pj1] + av1.y + Cv[j].w) * fw2.y;
                }
            }
        }
        __syncthreads();   // buffer handoff + S visibility
    }
}

extern "C" void kernel_launch(void* const* d_in, const int* in_sizes, int n_in,
                              void* d_out, int out_size)
{
    const float* w  = (const float*)d_in[0];
    const float* q  = (const float*)d_in[1];
    const float* k  = (const float*)d_in[2];
    const float* v  = (const float*)d_in[3];
    const float* a  = (const float*)d_in[4];
    const float* b  = (const float*)d_in[5];
    const float* s0 = (const float*)d_in[6];
    float* y = (float*)d_out;

    cudaFuncSetAttribute(rwkv7_kernel, cudaFuncAttributeMaxDynamicSharedMemorySize, SMEM_BYTES);
    rwkv7_kernel<<<B_ * H_, THREADS, SMEM_BYTES>>>(w, q, k, v, a, b, s0, y);
}

// round 17
// speedup vs baseline: 1.3864x; 1.3648x over previous
#include <cuda_runtime.h>
#include <cstdint>

// RWKV7 chunked attention, B=4 T=2048 H=32 C=64 dT=16.
// One CTA (512 thr) per (b,h). Producer/consumer pipeline.
// tf32 mma.sync for: state GEMM [wa;wq]@S^T, grams [wa;wq]@[bwi;kwi]^T,
// AKV/QKV [ak;qk]@v, ACCV v^T@kwi, ACCU u^T@bwi, and (R16) y = qb@u.
// Base is champion R12 verbatim; only the y phase + solve stores changed.

#define B_ 4
#define T_ 2048
#define H_ 32
#define C_ 64
#define DT_ 16
#define NT_ 128
#define THREADS 512

typedef unsigned long long u64;

// ---- shared layout (float words) ----
#define OFF_S    0          // [64][68] plain
#define OFF_UT   4352       // [64][17] tf32 u^T
#define OFF_ABU  5440       // [16][68] plain
#define OFF_YP   6528       // [16][68] plain
#define OFF_LPP  7616       // [4][64]
#define OFF_BUF  7872
// per-buffer offsets:
#define BWAQ 0              // [32][68] tf32 (wa rows 0-15, wq rows 16-31)
#define BKWQ 2176           // [32][68] tf32 (bwi rows 0-15, kwi rows 16-31)
#define BVT  4352           // [64][17] tf32 v^T
#define BKWT 5440           // [64][17] tf32 kwi^T
#define BBWT 6528           // [64][17] tf32 bwi^T
#define BAKV 7616           // [16][68] plain
#define BQKV 8704           // [16][68] plain
#define BD32 9792           // [32][36] masked grams (tf32): ab|ak / qb|qk
#define BFW  10944          // [64]
#define BUF_STRIDE 11008
#define OFF_ACCV (OFF_BUF + 2 * BUF_STRIDE)   // 2 x [64][68] plain (raw accv)
#define SMEM_WORDS (OFF_ACCV + 2 * 4352)
#define SMEM_BYTES (SMEM_WORDS * 4)

#define BARC() asm volatile("bar.sync 1, 256;" ::: "memory")   // consumer group
#define BARP() asm volatile("bar.sync 2, 256;" ::: "memory")   // producer group

__device__ __forceinline__ float4 ld4(const float* p) { return *reinterpret_cast<const float4*>(p); }
__device__ __forceinline__ void st4(float* p, float4 v) { *reinterpret_cast<float4*>(p) = v; }

__device__ __forceinline__ float tf32r(float x) {
    uint32_t r; asm("cvt.rna.tf32.f32 %0, %1;" : "=r"(r) : "f"(x));
    return __uint_as_float(r);
}
__device__ __forceinline__ void mma8f(float4& d, float a0, float a1, float a2,
                                      float a3, float b0, float b1) {
    asm volatile(
        "mma.sync.aligned.m16n8k8.row.col.f32.tf32.tf32.f32 "
        "{%0,%1,%2,%3}, {%4,%5,%6,%7}, {%8,%9}, {%0,%1,%2,%3};"
        : "+f"(d.x), "+f"(d.y), "+f"(d.z), "+f"(d.w)
        : "r"(__float_as_uint(a0)), "r"(__float_as_uint(a1)),
          "r"(__float_as_uint(a2)), "r"(__float_as_uint(a3)),
          "r"(__float_as_uint(b0)), "r"(__float_as_uint(b1)));
}

// ---------- producer (R12 verbatim) ----------
__device__ __forceinline__ void produce(
    float* __restrict__ sm, float* __restrict__ buf, float* __restrict__ av,
    const float* __restrict__ gw, const float* __restrict__ gq,
    const float* __restrict__ gk, const float* __restrict__ gv,
    const float* __restrict__ ga, const float* __restrict__ gb,
    int b, int h, int cp, int pt)
{
    const int th = pt >> 6;
    const int cl = pt & 63;
    const size_t strT = (size_t)H_ * C_;
    const int wmp  = pt >> 5;
    const int lane = pt & 31;
    const int gid  = lane >> 2;
    const int tq   = lane & 3;

    // ---- stage ----
    {
        size_t base = (((size_t)b * T_ + cp * DT_ + 4 * th) * H_ + h) * C_ + cl;
        float rw[4], rq[4], rk[4], rv[4], ra[4], rb[4];
        #pragma unroll
        for (int r = 0; r < 4; r++) {
            size_t ix = base + (size_t)r * strT;
            rw[r] = gw[ix]; rq[r] = gq[ix]; rk[r] = gk[ix];
            rv[r] = gv[ix]; ra[r] = ga[ix]; rb[r] = gb[ix];
        }
        float wd[4]; float lp = 1.f;
        #pragma unroll
        for (int r = 0; r < 4; r++) { wd[r] = __expf(-__expf(rw[r])); lp *= wd[r]; }
        sm[OFF_LPP + th * 64 + cl] = lp;
        BARP();
        float incl = 1.f;
        #pragma unroll
        for (int gg = 0; gg < 3; gg++)
            if (gg < th) incl *= sm[OFF_LPP + gg * 64 + cl];
        #pragma unroll
        for (int r = 0; r < 4; r++) {
            int t = 4 * th + r;
            float ip = incl; incl *= wd[r];
            float rinv = __fdividef(1.f, incl);
            float kw = tf32r(rk[r] * rinv);
            float bw = tf32r(rb[r] * rinv);
            buf[BWAQ + t * 68 + cl]        = tf32r(ra[r] * ip);
            buf[BWAQ + (16 + t) * 68 + cl] = tf32r(rq[r] * incl);
            buf[BKWQ + t * 68 + cl]        = bw;
            buf[BKWQ + (16 + t) * 68 + cl] = kw;
            buf[BVT  + cl * 17 + t] = tf32r(rv[r]);
            buf[BKWT + cl * 17 + t] = kw;
            buf[BBWT + cl * 17 + t] = bw;
        }
        if (th == 3) buf[BFW + cl] = incl;
    }
    BARP();

    // ---- grams via mma: D32 = [wa;wq] @ [bwi;kwi]^T ----
    {
        const int mt = wmp & 1;
        const int nb = wmp >> 1;
        const float* Ar = buf + BWAQ + (16 * mt + gid) * 68;
        const float* Br = buf + BKWQ + (8 * nb + gid) * 68;
        float4 Cv = {0.f, 0.f, 0.f, 0.f};
        #pragma unroll
        for (int k = 0; k < 8; k++) {
            const int ca = 8 * k + tq;
            mma8f(Cv, Ar[ca], Ar[8 * 68 + ca], Ar[ca + 4], Ar[8 * 68 + ca + 4],
                  Br[ca], Br[ca + 4]);
        }
        const int t0 = gid, t1 = gid + 8;
        const int C0 = 8 * nb + 2 * tq, C1 = C0 + 1;
        const int s0 = C0 & 15, s1 = C1 & 15;
        float m00, m01, m10, m11;
        if (mt == 0) { m00 = (t0 > s0); m01 = (t0 > s1); m10 = (t1 > s0); m11 = (t1 > s1); }
        else         { m00 = (t0 >= s0); m01 = (t0 >= s1); m10 = (t1 >= s0); m11 = (t1 >= s1); }
        float* D = buf + BD32;
        D[(16 * mt + gid)     * 36 + C0] = tf32r(Cv.x * m00);
        D[(16 * mt + gid)     * 36 + C1] = tf32r(Cv.y * m01);
        D[(16 * mt + gid + 8) * 36 + C0] = tf32r(Cv.z * m10);
        D[(16 * mt + gid + 8) * 36 + C1] = tf32r(Cv.w * m11);
    }
    BARP();

    // ---- AKV/QKV via mma: [ak;qk](32x16) @ v(16x64) ----
    {
        const int mt = wmp & 1;                 // 0 -> akv, 1 -> qkv
        const int n0 = 16 * (wmp >> 1);
        const float* Ar = buf + BD32 + (16 * mt + gid) * 36 + 16;
        float4 C0v = {0.f, 0.f, 0.f, 0.f};
        float4 C1v = {0.f, 0.f, 0.f, 0.f};
        #pragma unroll
        for (int k = 0; k < 2; k++) {
            const int ca = 8 * k + tq;
            float a0 = Ar[ca], a1 = Ar[8 * 36 + ca];
            float a2 = Ar[ca + 4], a3 = Ar[8 * 36 + ca + 4];
            float b00 = buf[BVT + (n0 + gid) * 17 + ca];
            float b01 = buf[BVT + (n0 + gid) * 17 + ca + 4];
            float b10 = buf[BVT + (n0 + 8 + gid) * 17 + ca];
            float b11 = buf[BVT + (n0 + 8 + gid) * 17 + ca + 4];
            mma8f(C0v, a0, a1, a2, a3, b00, b01);
            mma8f(C1v, a0, a1, a2, a3, b10, b11);
        }
        float* dst = buf + (mt == 0 ? BAKV : BQKV);
        *reinterpret_cast<float2*>(dst + gid * 68 + n0 + 2 * tq)           = make_float2(C0v.x, C0v.y);
        *reinterpret_cast<float2*>(dst + (gid + 8) * 68 + n0 + 2 * tq)     = make_float2(C0v.z, C0v.w);
        *reinterpret_cast<float2*>(dst + gid * 68 + n0 + 8 + 2 * tq)       = make_float2(C1v.x, C1v.y);
        *reinterpret_cast<float2*>(dst + (gid + 8) * 68 + n0 + 8 + 2 * tq) = make_float2(C1v.z, C1v.w);
    }

    // ---- ACCV via mma: v^T(64x16) @ kwi(16x64) -> av raw [64][68] ----
    {
        const int m0 = 16 * (wmp >> 1);
        const int nbase = 32 * (wmp & 1);
        float4 Cv[4] = {{0,0,0,0}, {0,0,0,0}, {0,0,0,0}, {0,0,0,0}};
        #pragma unroll
        for (int k = 0; k < 2; k++) {
            const int ca = 8 * k + tq;
            float a0 = buf[BVT + (m0 + gid) * 17 + ca];
            float a1 = buf[BVT + (m0 + gid + 8) * 17 + ca];
            float a2 = buf[BVT + (m0 + gid) * 17 + ca + 4];
            float a3 = buf[BVT + (m0 + gid + 8) * 17 + ca + 4];
            #pragma unroll
            for (int j = 0; j < 4; j++) {
                const int n = nbase + 8 * j;
                float b0 = buf[BKWT + (n + gid) * 17 + ca];
                float b1 = buf[BKWT + (n + gid) * 17 + ca + 4];
                mma8f(Cv[j], a0, a1, a2, a3, b0, b1);
            }
        }
        #pragma unroll
        for (int j = 0; j < 4; j++) {
            const int n = nbase + 8 * j;
            *reinterpret_cast<float2*>(av + (m0 + gid) * 68 + n + 2 * tq)     = make_float2(Cv[j].x, Cv[j].y);
            *reinterpret_cast<float2*>(av + (m0 + gid + 8) * 68 + n + 2 * tq) = make_float2(Cv[j].z, Cv[j].w);
        }
    }
}

__global__ __launch_bounds__(THREADS, 1)
void rwkv7_kernel(const float* __restrict__ gw, const float* __restrict__ gq,
                  const float* __restrict__ gk, const float* __restrict__ gv,
                  const float* __restrict__ ga, const float* __restrict__ gb,
                  const float* __restrict__ gs0, float* __restrict__ gy)
{
    extern __shared__ __align__(16) float sm[];

    const int bh  = blockIdx.x;
    const int b   = bh / H_;
    const int h   = bh % H_;
    const int tid = threadIdx.x;
    const bool is_prod = tid >= 256;
    const int pt = tid & 255;

    // consumer mappings
    const int w    = pt >> 5;
    const int lane = pt & 31;
    const int mt   = w & 1;
    const int nb   = w >> 1;
    const int gid  = lane >> 2;
    const int tq   = lane & 3;

    // ---- bootstrap ----
    if (is_prod) {
        produce(sm, sm + OFF_BUF, sm + OFF_ACCV, gw, gq, gk, gv, ga, gb, b, h, 0, pt);
    } else {
        const float* s0p = gs0 + (size_t)bh * 4096;
        #pragma unroll
        for (int q4 = pt; q4 < 1024; q4 += 256) {
            int row = q4 >> 4, f = q4 & 15;
            st4(sm + OFF_S + row * 68 + f * 4, ld4(s0p + row * 64 + f * 4));
        }
    }
    __syncthreads();

    for (int ch = 0; ch < NT_; ch++) {
        const int p = ch & 1;

        if (is_prod) {
            if (ch + 1 < NT_)
                produce(sm, sm + OFF_BUF + (p ^ 1) * BUF_STRIDE,
                        sm + OFF_ACCV + (p ^ 1) * 4352,
                        gw, gq, gk, gv, ga, gb, b, h, ch + 1, pt);
        } else {
            float* buf = sm + OFF_BUF + p * BUF_STRIDE;
            float* av  = sm + OFF_ACCV + p * 4352;

            // ===== state GEMM via mma: D = [wa;wq] @ S^T (R12 verbatim) =====
            {
                const float* Wr = buf + BWAQ + (16 * mt + gid) * 68;
                const int n0 = 16 * nb, n1 = n0 + 8;
                float4 C0 = {0.f, 0.f, 0.f, 0.f};
                float4 C1 = {0.f, 0.f, 0.f, 0.f};
                #pragma unroll
                for (int k = 0; k < 8; k++) {
                    const int ca = 8 * k + tq;
                    float a0 = Wr[ca], a1 = Wr[8 * 68 + ca];
                    float a2 = Wr[ca + 4], a3 = Wr[8 * 68 + ca + 4];
                    const float* S0 = sm + OFF_S + (n0 + gid) * 68 + ca;
                    const float* S1 = sm + OFF_S + (n1 + gid) * 68 + ca;
                    mma8f(C0, a0, a1, a2, a3, S0[0], S0[4]);
                    mma8f(C1, a0, a1, a2, a3, S1[0], S1[4]);
                }
                float* dst = (mt == 0) ? (sm + OFF_ABU) : (sm + OFF_YP);
                *reinterpret_cast<float2*>(dst + gid * 68 + n0 + 2 * tq)       = make_float2(C0.x, C0.y);
                *reinterpret_cast<float2*>(dst + (gid + 8) * 68 + n0 + 2 * tq) = make_float2(C0.z, C0.w);
                *reinterpret_cast<float2*>(dst + gid * 68 + n1 + 2 * tq)       = make_float2(C1.x, C1.y);
                *reinterpret_cast<float2*>(dst + (gid + 8) * 68 + n1 + 2 * tq) = make_float2(C1.z, C1.w);
            }
            BARC();   // abu/yp raw ready

            // ===== solve (I-ab) u = abu+AKV (64 columns, 2 warps) =====
            if (pt < 64) {
                const int c = pt;
                float uu[DT_];
                #pragma unroll
                for (int t = 0; t < DT_; t++)
                    uu[t] = sm[OFF_ABU + t * 68 + c] + buf[BAKV + t * 68 + c];
                #pragma unroll
                for (int t = 1; t < DT_; t++) {
                    float a0 = uu[t], a1 = 0.f, a2 = 0.f, a3 = 0.f;
                    const float* abr = buf + BD32 + t * 36;
                    #pragma unroll
                    for (int s4 = 0; 4 * s4 < t; s4++) {
                        float4 abq = ld4(abr + 4 * s4);
                        int s = 4 * s4;
                        if (s     < t) a0 += abq.x * uu[s];
                        if (s + 1 < t) a1 += abq.y * uu[s + 1];
                        if (s + 2 < t) a2 += abq.z * uu[s + 2];
                        if (s + 3 < t) a3 += abq.w * uu[s + 3];
                    }
                    uu[t] = (a0 + a1) + (a2 + a3);
                }
                #pragma unroll
                for (int t = 0; t < DT_; t++)
                    sm[OFF_UT + c * 17 + t] = tf32r(uu[t]);
            }
            BARC();   // u ready

            // ===== y via mma: y = qb@u + YP + QKV (R16) =====
            {
                const int n0 = 8 * w;            // this warp's 8 output columns
                const float* Ar = buf + BD32 + (16 + gid) * 36;   // qb rows
                float4 Cv = {0.f, 0.f, 0.f, 0.f};
                #pragma unroll
                for (int k = 0; k < 2; k++) {
                    const int ca = 8 * k + tq;
                    float a0 = Ar[ca], a1 = Ar[8 * 36 + ca];
                    float a2 = Ar[ca + 4], a3 = Ar[8 * 36 + ca + 4];
                    float b0 = sm[OFF_UT + (n0 + gid) * 17 + ca];
                    float b1 = sm[OFF_UT + (n0 + gid) * 17 + ca + 4];
                    mma8f(Cv, a0, a1, a2, a3, b0, b1);
                }
                const int c0 = n0 + 2 * tq;
                float2 yp0 = *reinterpret_cast<const float2*>(sm + OFF_YP + gid * 68 + c0);
                float2 yp1 = *reinterpret_cast<const float2*>(sm + OFF_YP + (gid + 8) * 68 + c0);
                float2 qk0 = *reinterpret_cast<const float2*>(buf + BQKV + gid * 68 + c0);
                float2 qk1 = *reinterpret_cast<const float2*>(buf + BQKV + (gid + 8) * 68 + c0);
                size_t y0 = (((size_t)b * T_ + ch * DT_ + gid) * H_ + h) * C_ + c0;
                size_t y1 = (((size_t)b * T_ + ch * DT_ + gid + 8) * H_ + h) * C_ + c0;
                __stcs(reinterpret_cast<float2*>(gy + y0),
                       make_float2(Cv.x + yp0.x + qk0.x, Cv.y + yp0.y + qk0.y));
                __stcs(reinterpret_cast<float2*>(gy + y1),
                       make_float2(Cv.z + yp1.x + qk1.x, Cv.w + yp1.y + qk1.y));
            }

            // ===== ACCU via mma + fused state update (R12 verbatim) =====
            {
                const int m0 = 16 * (w >> 1);
                const int nbase = 32 * (w & 1);
                float4 Cv[4] = {{0,0,0,0}, {0,0,0,0}, {0,0,0,0}, {0,0,0,0}};
                #pragma unroll
                for (int k = 0; k < 2; k++) {
                    const int ca = 8 * k + tq;
                    float a0 = sm[OFF_UT + (m0 + gid) * 17 + ca];
                    float a1 = sm[OFF_UT + (m0 + gid + 8) * 17 + ca];
                    float a2 = sm[OFF_UT + (m0 + gid) * 17 + ca + 4];
                    float a3 = sm[OFF_UT + (m0 + gid + 8) * 17 + ca + 4];
                    #pragma unroll
                    for (int j = 0; j < 4; j++) {
                        const int n = nbase + 8 * j;
                        float b0 = buf[BBWT + (n + gid) * 17 + ca];
                        float b1 = buf[BBWT + (n + gid) * 17 + ca + 4];
                        mma8f(Cv[j], a0, a1, a2, a3, b0, b1);
                    }
                }
                #pragma unroll
                for (int j = 0; j < 4; j++) {
                    const int n = nbase + 8 * j;
                    const int c0 = n + 2 * tq;
                    float2 fw2 = *reinterpret_cast<const float2*>(buf + BFW + c0);
                    float* s0p = sm + OFF_S + (m0 + gid) * 68 + c0;
                    float* s1p = sm + OFF_S + (m0 + gid + 8) * 68 + c0;
                    float2 av0 = *reinterpret_cast<const float2*>(av + (m0 + gid) * 68 + c0);
                    float2 av1 = *reinterpret_cast<const float2*>(av + (m0 + gid + 8) * 68 + c0);
                    float2 S0 = *reinterpret_cast<const float2*>(s0p);
                    float2 S1 = *reinterpret_cast<const float2*>(s1p);
                    S0.x = (S0.x + av0.x + Cv[j].x) * fw2.x;
                    S0.y = (S0.y + av0.y + Cv[j].y) * fw2.y;
                    S1.x = (S1.x + av1.x + Cv[j].z) * fw2.x;
                    S1.y = (S1.y + av1.y + Cv[j].w) * fw2.y;
                    *reinterpret_cast<float2*>(s0p) = S0;
                    *reinterpret_cast<float2*>(s1p) = S1;
                }
            }
        }
        __syncthreads();   // buffer handoff + S visibility
    }
}

extern "C" void kernel_launch(void* const* d_in, const int* in_sizes, int n_in,
                              void* d_out, int out_size)
{
    const float* w  = (const float*)d_in[0];
    const float* q  = (const float*)d_in[1];
    const float* k  = (const float*)d_in[2];
    const float* v  = (const float*)d_in[3];
    const float* a  = (const float*)d_in[4];
    const float* b  = (const float*)d_in[5];
    const float* s0 = (const float*)d_in[6];
    float* y = (float*)d_out;

    cudaFuncSetAttribute(rwkv7_kernel, cudaFuncAttributeMaxDynamicSharedMemorySize, SMEM_BYTES);
    rwkv7_kernel<<<B_ * H_, THREADS, SMEM_BYTES>>>(w, q, k, v, a, b, s0, y);
}